// round 13
// baseline (speedup 1.0000x reference)
#include <cuda_runtime.h>

#define N_NODES 48
#define N_EDGES 192
#define DIM     1024
#define NN      (N_NODES * N_NODES)   // 2304
#define EE      (N_EDGES * N_EDGES)   // 36864
#define OUT_DIM NN                    // 2304
#define SPLITK  32
#define KC      (DIM / SPLITK)        // 32
#define N4      ((OUT_DIM * OUT_DIM) / 4)   // 1,327,104 float4
#define GEMM_BLOCKS (9 * SPLITK)      // 288 (64-thread blocks)
#define MP_BLOCKS   192               // warp per 6 outputs, 2 warps/block
#define MAIN_BLOCKS (GEMM_BLOCKS + MP_BLOCKS)  // 480
#define PRE_BLOCKS  512               // 4 coeff rows each
#define PRE_THREADS 256

// Scratch (no cudaMalloc allowed)
__device__ float g_cn[DIM];
__device__ float g_ce[DIM];
__device__ float g_Mp[NN];
__device__ float g_MePart[SPLITK][EE];   // 4.7 MB, L2-resident

__device__ __forceinline__ float softplus_act(float x) {
    // relu(softplus(x) - 0.5)
    float sp = (x > 20.f) ? x : log1pf(expf(x));
    float v = sp - 0.5f;
    return v > 0.f ? v : 0.f;
}

// ---------------------------------------------------------------------------
// Kernel 1: coeff = tanh(W @ gw + b) (4 rows/block, 4 independent LDG.128
// per thread) + full 21MB zero-fill (stores hide under the load latency;
// this kernel's pipes are otherwise idle).
// ---------------------------------------------------------------------------
__global__ void __launch_bounds__(PRE_THREADS)
k_pre(const float* __restrict__ Wn, const float* __restrict__ bn,
      const float* __restrict__ We, const float* __restrict__ be,
      const float* __restrict__ gw, float4* __restrict__ out4) {
    __shared__ float sred[32];
    int t = threadIdx.x;
    int lane = t & 31, warp = t >> 5;
    int r0 = blockIdx.x * 4;                 // 0..2044, never straddles Wn/We
    const float* W;
    const float* bias;
    float* outp;
    int rr;
    if (r0 < DIM) { W = Wn; bias = bn; outp = g_cn; rr = r0; }
    else          { W = We; bias = be; outp = g_ce; rr = r0 - DIM; }

    const float4* p = (const float4*)(W + rr * DIM);  // row stride = 256 float4
    float4 a0 = p[t], a1 = p[256 + t], a2 = p[512 + t], a3 = p[768 + t];
    float4 g = ((const float4*)gw)[t];

    // zero-fill output (independent of the loads above)
    {
        float4 z = make_float4(0.f, 0.f, 0.f, 0.f);
        for (int i = blockIdx.x * PRE_THREADS + t; i < N4;
             i += PRE_BLOCKS * PRE_THREADS)
            out4[i] = z;
    }

    float s0 = a0.x * g.x + a0.y * g.y + a0.z * g.z + a0.w * g.w;
    float s1 = a1.x * g.x + a1.y * g.y + a1.z * g.z + a1.w * g.w;
    float s2 = a2.x * g.x + a2.y * g.y + a2.z * g.z + a2.w * g.w;
    float s3 = a3.x * g.x + a3.y * g.y + a3.z * g.z + a3.w * g.w;
#pragma unroll
    for (int o = 16; o; o >>= 1) {
        s0 += __shfl_xor_sync(0xffffffffu, s0, o);
        s1 += __shfl_xor_sync(0xffffffffu, s1, o);
        s2 += __shfl_xor_sync(0xffffffffu, s2, o);
        s3 += __shfl_xor_sync(0xffffffffu, s3, o);
    }
    if (lane == 0) {
        sred[0 * 8 + warp] = s0;
        sred[1 * 8 + warp] = s1;
        sred[2 * 8 + warp] = s2;
        sred[3 * 8 + warp] = s3;
    }
    __syncthreads();
    if (t < 4) {
        float s = 0.f;
#pragma unroll
        for (int j = 0; j < 8; j++) s += sred[t * 8 + j];
        outp[rr + t] = tanhf(s + bias[rr + t]);
    }
}

// ---------------------------------------------------------------------------
// Kernel 2 (64-thread blocks):
//   blocks 0..287   -> Me split-K(32) GEMM partials, 64x64 tile, 8x8 thread
//                      tile (1 MAC/byte of smem -> FFMA is the only binding
//                      pipe), k-major smem, 2 stages of 16.
//   blocks 288..479 -> Mp (48x48) into g_Mp, warp per 6 outputs.
// ---------------------------------------------------------------------------
__global__ void __launch_bounds__(64)
k_main(const float* __restrict__ ef1, const float* __restrict__ ef2,
       const float* __restrict__ x1, const float* __restrict__ x2) {
    int t = threadIdx.x;
    int b = blockIdx.x;

    if (b < GEMM_BLOCKS) {
        // ---- Me GEMM partial: C[m,n] = sum_k ef1[m,k]*ce[k]*ef2[n,k]
        __shared__ float As[16][64];    // k-major
        __shared__ float Bs[16][64];

        int tile = b % 9, kz = b / 9;   // kz 0..31
        int bx = tile % 3, by = tile / 3;
        int tx = t & 7, ty = t >> 3;    // 8x8 thread grid
        int k0 = kz * KC;
        float acc[8][8] = {};
        const float4* Arow = (const float4*)(ef1 + (by * 64 + t) * DIM);
        const float4* Brow = (const float4*)(ef2 + (bx * 64 + t) * DIM);
        const float4* Ce4  = (const float4*)g_ce;

#pragma unroll 1
        for (int s = 0; s < 2; s++) {
            int kb4 = (k0 >> 2) + s * 4;   // float4 index of this 16-k stage
            float4 a4[4], b4[4], c4[4];
#pragma unroll
            for (int i = 0; i < 4; i++) {
                c4[i] = Ce4[kb4 + i];
                a4[i] = Arow[kb4 + i];
                b4[i] = Brow[kb4 + i];
            }
            if (s) __syncthreads();        // protect smem reuse
#pragma unroll
            for (int i = 0; i < 4; i++) {
                As[i * 4 + 0][t] = a4[i].x * c4[i].x;
                As[i * 4 + 1][t] = a4[i].y * c4[i].y;
                As[i * 4 + 2][t] = a4[i].z * c4[i].z;
                As[i * 4 + 3][t] = a4[i].w * c4[i].w;
                Bs[i * 4 + 0][t] = b4[i].x;
                Bs[i * 4 + 1][t] = b4[i].y;
                Bs[i * 4 + 2][t] = b4[i].z;
                Bs[i * 4 + 3][t] = b4[i].w;
            }
            __syncthreads();
#pragma unroll
            for (int kk = 0; kk < 16; kk++) {
                float4 al = *(const float4*)&As[kk][ty * 8];
                float4 ah = *(const float4*)&As[kk][ty * 8 + 4];
                float4 bl = *(const float4*)&Bs[kk][tx * 8];
                float4 bh = *(const float4*)&Bs[kk][tx * 8 + 4];
                float a[8] = {al.x, al.y, al.z, al.w, ah.x, ah.y, ah.z, ah.w};
                float bb[8] = {bl.x, bl.y, bl.z, bl.w, bh.x, bh.y, bh.z, bh.w};
#pragma unroll
                for (int j = 0; j < 8; j++)
#pragma unroll
                    for (int i = 0; i < 8; i++)
                        acc[j][i] += a[j] * bb[i];
            }
        }

        float* outp = g_MePart[kz];
#pragma unroll
        for (int j = 0; j < 8; j++) {
            int m = by * 64 + ty * 8 + j;
            int n = bx * 64 + tx * 8;
            *(float4*)(outp + m * N_EDGES + n) =
                make_float4(acc[j][0], acc[j][1], acc[j][2], acc[j][3]);
            *(float4*)(outp + m * N_EDGES + n + 4) =
                make_float4(acc[j][4], acc[j][5], acc[j][6], acc[j][7]);
        }
    } else {
        // ---- Mp: 384 warps, 6 outputs per warp (same m, A row reused)
        int lane = t & 31, warp = t >> 5;
        int w = (b - GEMM_BLOCKS) * 2 + warp;   // 0..383
        int idx0 = w * 6;
        int m = idx0 / N_NODES, n0 = idx0 % N_NODES;  // 48 % 6 == 0 -> same m
        const float4* A  = (const float4*)(x1 + m * DIM);
        const float4* B0 = (const float4*)(x2 + n0 * DIM);
        const float4* C  = (const float4*)g_cn;
        float s[6] = {};
#pragma unroll
        for (int i = 0; i < 8; i++) {
            int k = i * 32 + lane;
            float4 a = A[k], c = C[k];
            a.x *= c.x; a.y *= c.y; a.z *= c.z; a.w *= c.w;
#pragma unroll
            for (int q = 0; q < 6; q++) {
                float4 bq = B0[q * 256 + k];
                s[q] += a.x * bq.x + a.y * bq.y + a.z * bq.z + a.w * bq.w;
            }
        }
#pragma unroll
        for (int o = 16; o; o >>= 1)
#pragma unroll
            for (int q = 0; q < 6; q++)
                s[q] += __shfl_xor_sync(0xffffffffu, s[q], o);
        if (lane == 0) {
#pragma unroll
            for (int q = 0; q < 6; q++)
                g_Mp[idx0 + q] = softplus_act(s[q]);
        }
    }
}

// ---------------------------------------------------------------------------
// Kernel 3: 4 outputs per thread; 32 independent LDG.128 partial loads,
// activate, scatter-add edges into M; then the diagonal from g_Mp.
// value for pair (j1,j2) is Me.flat[j2*192+j1]:
//   M[head2[j2]*48+head1[j1], tail2[j2]*48+tail1[j1]] += act(.)
// ---------------------------------------------------------------------------
__global__ void __launch_bounds__(128)
k_scatter(const int* __restrict__ ei1, const int* __restrict__ ei2,
          float* __restrict__ M) {
    int i = blockIdx.x * 128 + threadIdx.x;
    if (i < EE / 4) {
        int idx = i * 4;
        float4 sv = make_float4(0.f, 0.f, 0.f, 0.f);
#pragma unroll
        for (int z = 0; z < SPLITK; z++) {
            float4 p = *(const float4*)(g_MePart[z] + idx);
            sv.x += p.x; sv.y += p.y; sv.z += p.z; sv.w += p.w;
        }
        int j2 = idx / N_EDGES;           // same row for all 4 (192 % 4 == 0)
        int n0 = idx % N_EDGES;
        int rb = ei2[j2] * N_NODES;                 // head2*48
        int cb = ei2[N_EDGES + j2] * N_NODES;       // tail2*48
        float v0 = softplus_act(sv.x);
        float v1 = softplus_act(sv.y);
        float v2 = softplus_act(sv.z);
        float v3 = softplus_act(sv.w);
        if (v0 > 0.f)
            atomicAdd(M + (size_t)(rb + ei1[n0 + 0]) * OUT_DIM
                        + cb + ei1[N_EDGES + n0 + 0], v0);
        if (v1 > 0.f)
            atomicAdd(M + (size_t)(rb + ei1[n0 + 1]) * OUT_DIM
                        + cb + ei1[N_EDGES + n0 + 1], v1);
        if (v2 > 0.f)
            atomicAdd(M + (size_t)(rb + ei1[n0 + 2]) * OUT_DIM
                        + cb + ei1[N_EDGES + n0 + 2], v2);
        if (v3 > 0.f)
            atomicAdd(M + (size_t)(rb + ei1[n0 + 3]) * OUT_DIM
                        + cb + ei1[N_EDGES + n0 + 3], v3);
    } else if (i < EE / 4 + NN / 4) {
        int a0 = (i - EE / 4) * 4;
        float4 d = *(const float4*)(g_Mp + a0);
        atomicAdd(M + (size_t)(a0 + 0) * (OUT_DIM + 1), d.x);
        atomicAdd(M + (size_t)(a0 + 1) * (OUT_DIM + 1), d.y);
        atomicAdd(M + (size_t)(a0 + 2) * (OUT_DIM + 1), d.z);
        atomicAdd(M + (size_t)(a0 + 3) * (OUT_DIM + 1), d.w);
    }
}

extern "C" void kernel_launch(void* const* d_in, const int* in_sizes, int n_in,
                              void* d_out, int out_size) {
    const float* x1  = (const float*)d_in[0];
    const float* x2  = (const float*)d_in[1];
    const float* ef1 = (const float*)d_in[2];
    const float* ef2 = (const float*)d_in[3];
    const float* gw  = (const float*)d_in[4];
    const float* Wn  = (const float*)d_in[5];
    const float* bn  = (const float*)d_in[6];
    const float* We  = (const float*)d_in[7];
    const float* be  = (const float*)d_in[8];
    const int*   ei1 = (const int*)d_in[9];
    const int*   ei2 = (const int*)d_in[10];
    float* M = (float*)d_out;

    k_pre<<<PRE_BLOCKS, PRE_THREADS>>>(Wn, bn, We, be, gw, (float4*)M);
    k_main<<<MAIN_BLOCKS, 64>>>(ef1, ef2, x1, x2);
    int sc_threads = EE / 4 + NN / 4;               // 9792
    k_scatter<<<(sc_threads + 127) / 128, 128>>>(ei1, ei2, M);
}

// round 14
// speedup vs baseline: 1.0017x; 1.0017x over previous
#include <cuda_runtime.h>
#include <cstdint>

#define N_NODES 48
#define N_EDGES 192
#define DIM     1024
#define NN      (N_NODES * N_NODES)   // 2304
#define EE      (N_EDGES * N_EDGES)   // 36864
#define OUT_DIM NN                    // 2304
#define SPLITK  32
#define KC      (DIM / SPLITK)        // 32
#define N4      ((OUT_DIM * OUT_DIM) / 4)   // 1,327,104 float4
#define GEMM_BLOCKS (9 * SPLITK)      // 288
#define MP_BLOCKS   96
#define MAIN_BLOCKS (GEMM_BLOCKS + MP_BLOCKS)  // 384
#define PRE_BLOCKS  512               // 4 coeff rows each
#define PRE_THREADS 256

// Scratch (no cudaMalloc allowed)
__device__ float g_cn[DIM];
__device__ float g_ce[DIM];
__device__ float g_Mp[NN];
__device__ float g_MePart[SPLITK][EE];   // 4.7 MB, L2-resident

__device__ __forceinline__ float softplus_act(float x) {
    // relu(softplus(x) - 0.5)
    float sp = (x > 20.f) ? x : log1pf(expf(x));
    float v = sp - 0.5f;
    return v > 0.f ? v : 0.f;
}

__device__ __forceinline__ uint32_t smem_u32(const void* p) {
    uint32_t a;
    asm("{ .reg .u64 tmp; cvta.to.shared.u64 tmp, %1; cvt.u32.u64 %0, tmp; }"
        : "=r"(a) : "l"(p));
    return a;
}

// ---------------------------------------------------------------------------
// Kernel 1: coeff = tanh(W @ gw + b), 4 rows per block loaded with ONE
// cp.async.bulk (16KB -> smem, bypasses the per-thread LDG queue), plus the
// full 21MB zero-fill issued while the bulk copy is in flight.
// ---------------------------------------------------------------------------
__global__ void __launch_bounds__(PRE_THREADS)
k_pre(const float* __restrict__ Wn, const float* __restrict__ bn,
      const float* __restrict__ We, const float* __restrict__ be,
      const float* __restrict__ gw, float4* __restrict__ out4) {
    __shared__ float4 buf[1024];            // 16KB: 4 rows x 256 float4
    __shared__ float sred[32];
    __shared__ alignas(8) unsigned long long mbar;

    int t = threadIdx.x;
    int lane = t & 31, warp = t >> 5;
    int r0 = blockIdx.x * 4;                // 0..2044, never straddles Wn/We
    const float* W;
    const float* bias;
    float* outp;
    int rr;
    if (r0 < DIM) { W = Wn; bias = bn; outp = g_cn; rr = r0; }
    else          { W = We; bias = be; outp = g_ce; rr = r0 - DIM; }

    uint32_t mb = smem_u32(&mbar);
    uint32_t dst = smem_u32(buf);

    if (t == 0) {
        asm volatile("mbarrier.init.shared.b64 [%0], %1;" :: "r"(mb), "r"(1));
    }
    __syncthreads();
    if (t == 0) {
        asm volatile("mbarrier.arrive.expect_tx.shared.b64 _, [%0], %1;"
                     :: "r"(mb), "r"(16384u));
        const float* src = W + (size_t)rr * DIM;
        asm volatile(
            "cp.async.bulk.shared::cluster.global.mbarrier::complete_tx::bytes "
            "[%0], [%1], %2, [%3];"
            :: "r"(dst), "l"(src), "r"(16384u), "r"(mb) : "memory");
    }

    // gw load + zero-fill overlap the bulk copy
    float4 g = ((const float4*)gw)[t];
    {
        float4 z = make_float4(0.f, 0.f, 0.f, 0.f);
        for (int i = blockIdx.x * PRE_THREADS + t; i < N4;
             i += PRE_BLOCKS * PRE_THREADS)
            out4[i] = z;
    }

    // wait for the bulk copy (parity 0: fresh barrier each launch)
    {
        uint32_t done;
        do {
            asm volatile(
                "{\n\t.reg .pred p;\n\t"
                "mbarrier.try_wait.parity.acquire.cta.shared::cta.b64 p, [%1], %2;\n\t"
                "selp.b32 %0, 1, 0, p;\n\t}"
                : "=r"(done) : "r"(mb), "r"(0u) : "memory");
        } while (!done);
    }

    float4 a0 = buf[t], a1 = buf[256 + t], a2 = buf[512 + t], a3 = buf[768 + t];
    float s0 = a0.x * g.x + a0.y * g.y + a0.z * g.z + a0.w * g.w;
    float s1 = a1.x * g.x + a1.y * g.y + a1.z * g.z + a1.w * g.w;
    float s2 = a2.x * g.x + a2.y * g.y + a2.z * g.z + a2.w * g.w;
    float s3 = a3.x * g.x + a3.y * g.y + a3.z * g.z + a3.w * g.w;
#pragma unroll
    for (int o = 16; o; o >>= 1) {
        s0 += __shfl_xor_sync(0xffffffffu, s0, o);
        s1 += __shfl_xor_sync(0xffffffffu, s1, o);
        s2 += __shfl_xor_sync(0xffffffffu, s2, o);
        s3 += __shfl_xor_sync(0xffffffffu, s3, o);
    }
    if (lane == 0) {
        sred[0 * 8 + warp] = s0;
        sred[1 * 8 + warp] = s1;
        sred[2 * 8 + warp] = s2;
        sred[3 * 8 + warp] = s3;
    }
    __syncthreads();
    if (t < 4) {
        float s = 0.f;
#pragma unroll
        for (int j = 0; j < 8; j++) s += sred[t * 8 + j];
        outp[rr + t] = tanhf(s + bias[rr + t]);
    }
}

// ---------------------------------------------------------------------------
// Kernel 2: blocks 0..287  -> Me split-K(32) GEMM partials, 64x64 tile,
//           k-major smem, contiguous 4x4 C tile per thread. BOTH K-stages'
//           global operands are prefetched before the first smem store, so
//           the mainloop never waits on global memory.
//           blocks 288..383 -> Mp (48x48) into g_Mp scratch.
// ---------------------------------------------------------------------------
__global__ void __launch_bounds__(256, 2)
k_main(const float* __restrict__ ef1, const float* __restrict__ ef2,
       const float* __restrict__ x1, const float* __restrict__ x2) {
    int t = threadIdx.x;
    int b = blockIdx.x;

    if (b < GEMM_BLOCKS) {
        // ---- Me GEMM partial: C[m,n] = sum_k ef1[m,k]*ce[k]*ef2[n,k]
        __shared__ float4 As[16][17];   // [kk][rowgroup]
        __shared__ float4 Bs[16][17];
        float* Asf = (float*)As;        // row stride 68 floats
        float* Bsf = (float*)Bs;

        int tx = t & 15, ty = t >> 4;
        int bx = b % 3;
        int by = (b / 3) % 3;
        int kz = b / 9;                 // 0..31
        int lr = t >> 2;                // 0..63 (tile row this thread loads)
        int lc = (t & 3) * 4;           // 0,4,8,12 (k-chunk base)
        int k0 = kz * KC;
        const float* Arow = ef1 + (by * 64 + lr) * DIM;
        const float* Brow = ef2 + (bx * 64 + lr) * DIM;

        // prefetch both stages (6 independent LDG.128)
        float4 pa[2], pb[2], pc[2];
#pragma unroll
        for (int s = 0; s < 2; s++) {
            int kb = k0 + s * 16 + lc;
            pc[s] = *(const float4*)(g_ce + kb);
            pa[s] = *(const float4*)(Arow + kb);
            pb[s] = *(const float4*)(Brow + kb);
        }

        float acc[4][4] = {};
#pragma unroll
        for (int s = 0; s < 2; s++) {
            float4 a4 = pa[s], b4 = pb[s], c4 = pc[s];
            a4.x *= c4.x; a4.y *= c4.y; a4.z *= c4.z; a4.w *= c4.w;
            if (s) __syncthreads();
            Asf[(lc + 0) * 68 + lr] = a4.x;
            Asf[(lc + 1) * 68 + lr] = a4.y;
            Asf[(lc + 2) * 68 + lr] = a4.z;
            Asf[(lc + 3) * 68 + lr] = a4.w;
            Bsf[(lc + 0) * 68 + lr] = b4.x;
            Bsf[(lc + 1) * 68 + lr] = b4.y;
            Bsf[(lc + 2) * 68 + lr] = b4.z;
            Bsf[(lc + 3) * 68 + lr] = b4.w;
            __syncthreads();
#pragma unroll
            for (int kk = 0; kk < 16; kk++) {
                float4 av = As[kk][ty];
                float4 bv = Bs[kk][tx];
                float a[4] = {av.x, av.y, av.z, av.w};
                float bb[4] = {bv.x, bv.y, bv.z, bv.w};
#pragma unroll
                for (int j = 0; j < 4; j++)
#pragma unroll
                    for (int i = 0; i < 4; i++)
                        acc[j][i] += a[j] * bb[i];
            }
        }

        float* outp = g_MePart[kz];
#pragma unroll
        for (int j = 0; j < 4; j++) {
            int m = by * 64 + 4 * ty + j;
            int n = bx * 64 + 4 * tx;
            *(float4*)(outp + m * N_EDGES + n) =
                make_float4(acc[j][0], acc[j][1], acc[j][2], acc[j][3]);
        }
    } else {
        // ---- Mp: 768 warps, 3 outputs per warp, into g_Mp scratch.
        int lane = t & 31, warp = t >> 5;
        int w = (b - GEMM_BLOCKS) * 8 + warp;   // 0..767
        int idx0 = w * 3;
        int m = idx0 / N_NODES, n0 = idx0 % N_NODES;  // same m across the 3
        const float4* A  = (const float4*)(x1 + m * DIM);
        const float4* B0 = (const float4*)(x2 + n0 * DIM);
        const float4* C  = (const float4*)g_cn;
        float s0 = 0.f, s1 = 0.f, s2 = 0.f;
#pragma unroll
        for (int i = 0; i < 8; i++) {
            int k = i * 32 + lane;
            float4 a = A[k], c = C[k];
            a.x *= c.x; a.y *= c.y; a.z *= c.z; a.w *= c.w;
            float4 b0 = B0[k], b1 = B0[256 + k], b2 = B0[512 + k];
            s0 += a.x * b0.x + a.y * b0.y + a.z * b0.z + a.w * b0.w;
            s1 += a.x * b1.x + a.y * b1.y + a.z * b1.z + a.w * b1.w;
            s2 += a.x * b2.x + a.y * b2.y + a.z * b2.z + a.w * b2.w;
        }
#pragma unroll
        for (int o = 16; o; o >>= 1) {
            s0 += __shfl_xor_sync(0xffffffffu, s0, o);
            s1 += __shfl_xor_sync(0xffffffffu, s1, o);
            s2 += __shfl_xor_sync(0xffffffffu, s2, o);
        }
        if (lane == 0) {
            g_Mp[idx0 + 0] = softplus_act(s0);
            g_Mp[idx0 + 1] = softplus_act(s1);
            g_Mp[idx0 + 2] = softplus_act(s2);
        }
    }
}

// ---------------------------------------------------------------------------
// Kernel 3: 4 outputs per thread; 32 independent LDG.128 partial loads,
// activate, scatter-add edges into M; then the diagonal from g_Mp.
// value for pair (j1,j2) is Me.flat[j2*192+j1]:
//   M[head2[j2]*48+head1[j1], tail2[j2]*48+tail1[j1]] += act(.)
// ---------------------------------------------------------------------------
__global__ void __launch_bounds__(128)
k_scatter(const int* __restrict__ ei1, const int* __restrict__ ei2,
          float* __restrict__ M) {
    int i = blockIdx.x * 128 + threadIdx.x;
    if (i < EE / 4) {
        int idx = i * 4;
        float4 sv = make_float4(0.f, 0.f, 0.f, 0.f);
#pragma unroll
        for (int z = 0; z < SPLITK; z++) {
            float4 p = *(const float4*)(g_MePart[z] + idx);
            sv.x += p.x; sv.y += p.y; sv.z += p.z; sv.w += p.w;
        }
        int j2 = idx / N_EDGES;           // same row for all 4 (192 % 4 == 0)
        int n0 = idx % N_EDGES;
        int rb = ei2[j2] * N_NODES;                 // head2*48
        int cb = ei2[N_EDGES + j2] * N_NODES;       // tail2*48
        float v0 = softplus_act(sv.x);
        float v1 = softplus_act(sv.y);
        float v2 = softplus_act(sv.z);
        float v3 = softplus_act(sv.w);
        if (v0 > 0.f)
            atomicAdd(M + (size_t)(rb + ei1[n0 + 0]) * OUT_DIM
                        + cb + ei1[N_EDGES + n0 + 0], v0);
        if (v1 > 0.f)
            atomicAdd(M + (size_t)(rb + ei1[n0 + 1]) * OUT_DIM
                        + cb + ei1[N_EDGES + n0 + 1], v1);
        if (v2 > 0.f)
            atomicAdd(M + (size_t)(rb + ei1[n0 + 2]) * OUT_DIM
                        + cb + ei1[N_EDGES + n0 + 2], v2);
        if (v3 > 0.f)
            atomicAdd(M + (size_t)(rb + ei1[n0 + 3]) * OUT_DIM
                        + cb + ei1[N_EDGES + n0 + 3], v3);
    } else if (i < EE / 4 + NN / 4) {
        int a0 = (i - EE / 4) * 4;
        float4 d = *(const float4*)(g_Mp + a0);
        atomicAdd(M + (size_t)(a0 + 0) * (OUT_DIM + 1), d.x);
        atomicAdd(M + (size_t)(a0 + 1) * (OUT_DIM + 1), d.y);
        atomicAdd(M + (size_t)(a0 + 2) * (OUT_DIM + 1), d.z);
        atomicAdd(M + (size_t)(a0 + 3) * (OUT_DIM + 1), d.w);
    }
}

extern "C" void kernel_launch(void* const* d_in, const int* in_sizes, int n_in,
                              void* d_out, int out_size) {
    const float* x1  = (const float*)d_in[0];
    const float* x2  = (const float*)d_in[1];
    const float* ef1 = (const float*)d_in[2];
    const float* ef2 = (const float*)d_in[3];
    const float* gw  = (const float*)d_in[4];
    const float* Wn  = (const float*)d_in[5];
    const float* bn  = (const float*)d_in[6];
    const float* We  = (const float*)d_in[7];
    const float* be  = (const float*)d_in[8];
    const int*   ei1 = (const int*)d_in[9];
    const int*   ei2 = (const int*)d_in[10];
    float* M = (float*)d_out;

    k_pre<<<PRE_BLOCKS, PRE_THREADS>>>(Wn, bn, We, be, gw, (float4*)M);
    k_main<<<MAIN_BLOCKS, 256>>>(ef1, ef2, x1, x2);
    int sc_threads = EE / 4 + NN / 4;               // 9792
    k_scatter<<<(sc_threads + 127) / 128, 128>>>(ei1, ei2, M);
}